// round 9
// baseline (speedup 1.0000x reference)
#include <cuda_runtime.h>
#include <cuda_bf16.h>

// StandardDeviationPooling: 4x4 window, stride 2, VALID.
// Input:  [64, 1024, 1024, 1] fp32   Output: [64, 511*511] fp32
// std = sqrt(max(E[x^2] - E[x]^2, 0)) per window.
//
// R9: convergence build. R1 structure (best measured kernel time: no barriers,
// no smem, no shuffles; 2 output cols/thread from two float4 loads/row with
// L1-absorbed overlap; rolling 2-row pair sums so each input row is loaded
// once per strip) with:
//  - ROWS_PER_THREAD=14 -> 37 strips -> grid 2368 CTAs = exactly 2 waves
//    at 8 CTAs/SM x 148 SMs (kills wave-tail quantization), and lower
//    strip-boundary re-read ratio (2/30 vs 2/18).
//  - __stcs streaming stores (zero-reuse output keeps L2 for input overlap).
// Measured plateau: ~6.0 TB/s on this 79%R/21%W mixed stream, traffic within
// ~1.5% of the 323 MB floor.

#define H_IN 1024
#define W_IN 1024
#define H_OUT 511
#define W_OUT 511
#define ROWS_PER_THREAD 14

__global__ __launch_bounds__(256, 8)
void std_pool_kernel(const float* __restrict__ in, float* __restrict__ out) {
    const int c  = threadIdx.x;                 // col-pair index 0..255
    const int r0 = blockIdx.y * ROWS_PER_THREAD;
    const int b  = blockIdx.z;

    const float* __restrict__ inb  = in  + (size_t)b * H_IN * W_IN;
    float* __restrict__       outb = out + (size_t)b * H_OUT * W_OUT;

    const int  ic   = 4 * c;                 // first input col
    const bool has2 = (ic + 7) < W_IN;       // second float4 in-bounds (c < 255)
    const int  oc0  = 2 * c;
    const float inv_n = 1.0f / 16.0f;

    // previous row-pair sums/sumsq for the 2 output cols
    float ps0 = 0.f, ps1 = 0.f, pq0 = 0.f, pq1 = 0.f;

    #pragma unroll
    for (int j = 0; j <= ROWS_PER_THREAD; ++j) {
        const int irow = 2 * (r0 + j);
        float cs0 = 0.f, cs1 = 0.f, cq0 = 0.f, cq1 = 0.f;

        if (irow + 1 < H_IN) {
            #pragma unroll
            for (int rr = 0; rr < 2; ++rr) {
                const float* rowp = inb + (size_t)(irow + rr) * W_IN + ic;
                const float4 a = *reinterpret_cast<const float4*>(rowp);
                float4 d;
                if (has2) d = *reinterpret_cast<const float4*>(rowp + 4);
                else      d = make_float4(0.f, 0.f, 0.f, 0.f);

                cs0 += a.x + a.y + a.z + a.w;
                cq0 = fmaf(a.x, a.x, fmaf(a.y, a.y, fmaf(a.z, a.z, fmaf(a.w, a.w, cq0))));
                cs1 += a.z + a.w + d.x + d.y;
                cq1 = fmaf(a.z, a.z, fmaf(a.w, a.w, fmaf(d.x, d.x, fmaf(d.y, d.y, cq1))));
            }
        }

        if (j > 0) {
            const int orow = r0 + j - 1;
            if (orow < H_OUT) {
                float* orow_p = outb + (size_t)orow * W_OUT;
                {
                    const float s = ps0 + cs0, q = pq0 + cq0;
                    const float m = s * inv_n;
                    __stcs(orow_p + oc0, sqrtf(fmaxf(fmaf(-m, m, q * inv_n), 0.f)));
                }
                if (oc0 + 1 < W_OUT) {
                    const float s = ps1 + cs1, q = pq1 + cq1;
                    const float m = s * inv_n;
                    __stcs(orow_p + oc0 + 1, sqrtf(fmaxf(fmaf(-m, m, q * inv_n), 0.f)));
                }
            }
        }
        ps0 = cs0; ps1 = cs1; pq0 = cq0; pq1 = cq1;
    }
}

extern "C" void kernel_launch(void* const* d_in, const int* in_sizes, int n_in,
                              void* d_out, int out_size) {
    const float* in = (const float*)d_in[0];
    float* out = (float*)d_out;
    (void)in_sizes; (void)n_in; (void)out_size;

    // 256 col-pair threads cover 511 output cols; 37 strips of 14 rows; 64 batches.
    // 37*64 = 2368 CTAs = exactly 2 waves at 8 CTAs/SM x 148 SMs.
    dim3 block(256, 1, 1);
    dim3 grid(1, (H_OUT + ROWS_PER_THREAD - 1) / ROWS_PER_THREAD, 64);
    std_pool_kernel<<<grid, block>>>(in, out);
}

// round 10
// speedup vs baseline: 1.0360x; 1.0360x over previous
#include <cuda_runtime.h>
#include <cuda_bf16.h>

// StandardDeviationPooling: 4x4 window, stride 2, VALID.
// Input:  [64, 1024, 1024, 1] fp32   Output: [64, 511*511] fp32
// std = sqrt(max(E[x^2] - E[x]^2, 0)) per window.
//
// R10: R9 (best measured: no barriers/smem/shuffles, 2 output cols/thread,
// rolling 2-row pair sums, RPT=14 -> 2368 CTAs = exact 2 waves @ occ 8,
// __stcs stores) + BOUSTROPHEDON strips: odd strips iterate rows bottom-up.
// Adjacent strips then touch their shared boundary row-pair at the SAME
// execution phase (end/end or start/start), so the 2-of-28-rows strip-overlap
// re-read hits L2 instead of DRAM (~13 MB of the 336 MB stream removed).

#define H_IN 1024
#define W_IN 1024
#define H_OUT 511
#define W_OUT 511
#define ROWS_PER_THREAD 14

__global__ __launch_bounds__(256, 8)
void std_pool_kernel(const float* __restrict__ in, float* __restrict__ out) {
    const int c     = threadIdx.x;                 // col-pair index 0..255
    const int strip = blockIdx.y;
    const int r0    = strip * ROWS_PER_THREAD;
    const int b     = blockIdx.z;
    const bool asc  = (strip & 1) == 0;            // boustrophedon direction

    const float* __restrict__ inb  = in  + (size_t)b * H_IN * W_IN;
    float* __restrict__       outb = out + (size_t)b * H_OUT * W_OUT;

    const int  ic   = 4 * c;                 // first input col
    const bool has2 = (ic + 7) < W_IN;       // second float4 in-bounds (c < 255)
    const int  oc0  = 2 * c;
    const float inv_n = 1.0f / 16.0f;

    // previously-visited row-pair sums/sumsq for the 2 output cols
    float ps0 = 0.f, ps1 = 0.f, pq0 = 0.f, pq1 = 0.f;

    #pragma unroll
    for (int t = 0; t <= ROWS_PER_THREAD; ++t) {
        // pair index within strip: ascending visits 0..RPT, descending RPT..0
        const int p    = asc ? t : (ROWS_PER_THREAD - t);
        const int irow = 2 * (r0 + p);
        float cs0 = 0.f, cs1 = 0.f, cq0 = 0.f, cq1 = 0.f;

        if (irow + 1 < H_IN) {
            #pragma unroll
            for (int rr = 0; rr < 2; ++rr) {
                const float* rowp = inb + (size_t)(irow + rr) * W_IN + ic;
                const float4 a = *reinterpret_cast<const float4*>(rowp);
                float4 d;
                if (has2) d = *reinterpret_cast<const float4*>(rowp + 4);
                else      d = make_float4(0.f, 0.f, 0.f, 0.f);

                cs0 += a.x + a.y + a.z + a.w;
                cq0 = fmaf(a.x, a.x, fmaf(a.y, a.y, fmaf(a.z, a.z, fmaf(a.w, a.w, cq0))));
                cs1 += a.z + a.w + d.x + d.y;
                cq1 = fmaf(a.z, a.z, fmaf(a.w, a.w, fmaf(d.x, d.x, fmaf(d.y, d.y, cq1))));
            }
        }

        if (t > 0) {
            // ascending: output row uses pairs (p-1, p)  -> orow = r0 + t - 1
            // descending: output row uses pairs (p, p+1) -> orow = r0 + p
            const int orow = asc ? (r0 + t - 1) : (r0 + p);
            if (orow < H_OUT) {
                float* orow_p = outb + (size_t)orow * W_OUT;
                {
                    const float s = ps0 + cs0, q = pq0 + cq0;
                    const float m = s * inv_n;
                    __stcs(orow_p + oc0, sqrtf(fmaxf(fmaf(-m, m, q * inv_n), 0.f)));
                }
                if (oc0 + 1 < W_OUT) {
                    const float s = ps1 + cs1, q = pq1 + cq1;
                    const float m = s * inv_n;
                    __stcs(orow_p + oc0 + 1, sqrtf(fmaxf(fmaf(-m, m, q * inv_n), 0.f)));
                }
            }
        }
        ps0 = cs0; ps1 = cs1; pq0 = cq0; pq1 = cq1;
    }
}

extern "C" void kernel_launch(void* const* d_in, const int* in_sizes, int n_in,
                              void* d_out, int out_size) {
    const float* in = (const float*)d_in[0];
    float* out = (float*)d_out;
    (void)in_sizes; (void)n_in; (void)out_size;

    // 256 col-pair threads cover 511 output cols; 37 strips of 14 rows; 64 batches.
    // 37*64 = 2368 CTAs = exactly 2 waves at 8 CTAs/SM x 148 SMs.
    dim3 block(256, 1, 1);
    dim3 grid(1, (H_OUT + ROWS_PER_THREAD - 1) / ROWS_PER_THREAD, 64);
    std_pool_kernel<<<grid, block>>>(in, out);
}